// round 1
// baseline (speedup 1.0000x reference)
#include <cuda_runtime.h>
#include <math.h>

#define B_    32
#define N_    1024
#define D_    128
#define ROW_  (N_ * D_)        // 131072 elements per batch row (sorted)
#define TOT_  (B_ * ROW_)      // 4194304 elements per tensor
#define CHUNK 8192             // bitonic shared-memory chunk (2^13)
#define LOG_ROW 17

// ---------------- scratch (static device globals: no allocs allowed) -------
__device__ float  g_sort[2 * TOT_];    // rows 0..31 = pred, 32..63 = target (32 MB)
__device__ float  g_normP[B_ * N_];
__device__ float  g_normG[B_ * N_];
__device__ int    g_colmin[B_ * N_];   // min over n per (b,m), float bits
__device__ int    g_minB[N_ * N_];     // min over b per (n,m), float bits (4 MB)
__device__ double g_acc[3];            // 0: mae sum, 1: colmin sum, 2: minB sum
__device__ double g_emd[B_];

// ---------------- helpers ---------------------------------------------------
__device__ __forceinline__ double blockReduceSum(double v) {
    __shared__ double s[32];
    int lane = threadIdx.x & 31, w = threadIdx.x >> 5;
    #pragma unroll
    for (int o = 16; o; o >>= 1) v += __shfl_down_sync(0xffffffffu, v, o);
    if (lane == 0) s[w] = v;
    __syncthreads();
    int nw = (blockDim.x + 31) >> 5;
    v = (threadIdx.x < nw) ? s[threadIdx.x] : 0.0;
    if (w == 0) {
        #pragma unroll
        for (int o = 16; o; o >>= 1) v += __shfl_down_sync(0xffffffffu, v, o);
    }
    return v;
}

// ---------------- init -------------------------------------------------------
__global__ void init_kernel() {
    int tid = blockIdx.x * blockDim.x + threadIdx.x;
    int stride = gridDim.x * blockDim.x;
    for (int i = tid; i < N_ * N_; i += stride) g_minB[i] = 0x7F800000;
    for (int i = tid; i < B_ * N_; i += stride) g_colmin[i] = 0x7F800000;
    if (tid < 3)  g_acc[tid] = 0.0;
    if (tid < B_) g_emd[tid] = 0.0;
}

// ---------------- MAE + copy into sort buffer --------------------------------
__global__ void mae_copy_kernel(const float* __restrict__ pred,
                                const float* __restrict__ tgt) {
    int tid = blockIdx.x * blockDim.x + threadIdx.x;
    int stride = gridDim.x * blockDim.x;
    double local = 0.0;
    for (int i = tid; i < TOT_; i += stride) {
        float p = pred[i], g = tgt[i];
        g_sort[i] = p;
        g_sort[TOT_ + i] = g;
        local += (double)fabsf(p - g);
    }
    double s = blockReduceSum(local);
    if (threadIdx.x == 0) atomicAdd(&g_acc[0], s);
}

// ---------------- row squared norms ------------------------------------------
__global__ void norms_kernel(const float* __restrict__ pred,
                             const float* __restrict__ tgt) {
    int gw = (blockIdx.x * blockDim.x + threadIdx.x) >> 5;
    int lane = threadIdx.x & 31;
    if (gw >= 2 * B_ * N_) return;
    const float* src = (gw < B_ * N_) ? pred : tgt;
    int row = gw & (B_ * N_ - 1);
    const float* p = src + (size_t)row * D_;
    float v0 = p[lane], v1 = p[lane + 32], v2 = p[lane + 64], v3 = p[lane + 96];
    float s = v0 * v0 + v1 * v1 + v2 * v2 + v3 * v3;
    #pragma unroll
    for (int o = 16; o; o >>= 1) s += __shfl_down_sync(0xffffffffu, s, o);
    if (lane == 0) ((gw < B_ * N_) ? g_normP : g_normG)[row] = s;
}

// ---------------- distance GEMM + fused min reductions -----------------------
// grid (8 m-tiles, 8 n-tiles, 4 batch-groups), block 256 (16x16), 8x8 micro.
__global__ void __launch_bounds__(256, 1)
dist_kernel(const float* __restrict__ pred, const float* __restrict__ tgt) {
    __shared__ float As[32][129];   // As[k][n] transposed, pad 1 -> conflict-free
    __shared__ float Bs[32][129];
    const int tx = threadIdx.x & 15;
    const int ty = threadIdx.x >> 4;
    const int tm = blockIdx.x, tn = blockIdx.y;

    float rmin[8][8];
    #pragma unroll
    for (int i = 0; i < 8; i++)
        #pragma unroll
        for (int j = 0; j < 8; j++) rmin[i][j] = __int_as_float(0x7F800000);

    for (int bb = 0; bb < 8; ++bb) {
        int b = blockIdx.z * 8 + bb;
        const float* A  = pred + ((size_t)b * N_ + tn * 128) * D_;
        const float* Bp = tgt  + ((size_t)b * N_ + tm * 128) * D_;

        float acc[8][8];
        #pragma unroll
        for (int i = 0; i < 8; i++)
            #pragma unroll
            for (int j = 0; j < 8; j++) acc[i][j] = 0.f;

        for (int kc = 0; kc < D_; kc += 32) {
            __syncthreads();
            #pragma unroll
            for (int it = 0; it < 4; ++it) {
                int e = threadIdx.x + it * 256;         // 1024 float4 slots
                int r = e >> 3, kq = e & 7;
                float4 va = *reinterpret_cast<const float4*>(A + r * D_ + kc + kq * 4);
                As[kq * 4 + 0][r] = va.x; As[kq * 4 + 1][r] = va.y;
                As[kq * 4 + 2][r] = va.z; As[kq * 4 + 3][r] = va.w;
                float4 vb = *reinterpret_cast<const float4*>(Bp + r * D_ + kc + kq * 4);
                Bs[kq * 4 + 0][r] = vb.x; Bs[kq * 4 + 1][r] = vb.y;
                Bs[kq * 4 + 2][r] = vb.z; Bs[kq * 4 + 3][r] = vb.w;
            }
            __syncthreads();
            #pragma unroll 4
            for (int k = 0; k < 32; ++k) {
                float ra[8], rb[8];
                #pragma unroll
                for (int i = 0; i < 8; i++) ra[i] = As[k][ty + 16 * i];
                #pragma unroll
                for (int j = 0; j < 8; j++) rb[j] = Bs[k][tx + 16 * j];
                #pragma unroll
                for (int i = 0; i < 8; i++)
                    #pragma unroll
                    for (int j = 0; j < 8; j++)
                        acc[i][j] = fmaf(ra[i], rb[j], acc[i][j]);
            }
        }

        float nA[8], nB[8], cmin[8];
        #pragma unroll
        for (int i = 0; i < 8; i++) nA[i] = g_normP[b * N_ + tn * 128 + ty + 16 * i];
        #pragma unroll
        for (int j = 0; j < 8; j++) {
            nB[j] = g_normG[b * N_ + tm * 128 + tx + 16 * j];
            cmin[j] = __int_as_float(0x7F800000);
        }
        #pragma unroll
        for (int i = 0; i < 8; i++)
            #pragma unroll
            for (int j = 0; j < 8; j++) {
                float sq = nA[i] + nB[j] - 2.f * acc[i][j];
                float d = sqrtf(fmaxf(sq, 1e-12f));
                rmin[i][j] = fminf(rmin[i][j], d);
                cmin[j]    = fminf(cmin[j], d);
            }

        // reduce cmin over ty (16 rows) in shared, then atomicMin to g_colmin
        __syncthreads();
        float* red = &As[0][0];       // needs 16*128 floats, As has 32*129
        #pragma unroll
        for (int j = 0; j < 8; j++) red[ty * 128 + tx + 16 * j] = cmin[j];
        __syncthreads();
        #pragma unroll
        for (int s = 8; s >= 1; s >>= 1) {
            if (ty < s) {
                #pragma unroll
                for (int j = 0; j < 8; j++) {
                    int ml = tx + 16 * j;
                    red[ty * 128 + ml] = fminf(red[ty * 128 + ml],
                                               red[(ty + s) * 128 + ml]);
                }
            }
            __syncthreads();
        }
        if (ty == 0) {
            #pragma unroll
            for (int j = 0; j < 8; j++) {
                int m = tm * 128 + tx + 16 * j;
                atomicMin(&g_colmin[b * N_ + m], __float_as_int(red[tx + 16 * j]));
            }
        }
    }

    // min over b: one atomicMin per element (4 contenders per address, z-groups)
    #pragma unroll
    for (int i = 0; i < 8; i++)
        #pragma unroll
        for (int j = 0; j < 8; j++) {
            int n = tn * 128 + ty + 16 * i;
            int m = tm * 128 + tx + 16 * j;
            atomicMin(&g_minB[n * N_ + m], __float_as_int(rmin[i][j]));
        }
}

// ---------------- chamfer reductions ------------------------------------------
__global__ void reduce_colmin_kernel() {
    int tid = blockIdx.x * blockDim.x + threadIdx.x, stride = gridDim.x * blockDim.x;
    double local = 0.0;
    for (int i = tid; i < B_ * N_; i += stride) local += (double)__int_as_float(g_colmin[i]);
    double s = blockReduceSum(local);
    if (threadIdx.x == 0) atomicAdd(&g_acc[1], s);
}
__global__ void reduce_minB_kernel() {
    int tid = blockIdx.x * blockDim.x + threadIdx.x, stride = gridDim.x * blockDim.x;
    double local = 0.0;
    for (int i = tid; i < N_ * N_; i += stride) local += (double)__int_as_float(g_minB[i]);
    double s = blockReduceSum(local);
    if (threadIdx.x == 0) atomicAdd(&g_acc[2], s);
}

// ---------------- bitonic sort (64 rows of 131072) -----------------------------
__global__ void __launch_bounds__(1024) bitonic_local_sort() {
    __shared__ float s[CHUNK];
    size_t base = (size_t)blockIdx.x * CHUNK;
    unsigned gbase = (unsigned)(base & (ROW_ - 1));
    for (int t = threadIdx.x; t < CHUNK; t += 1024) s[t] = g_sort[base + t];
    __syncthreads();
    for (unsigned k = 2; k <= CHUNK; k <<= 1) {
        for (unsigned j = k >> 1; j > 0; j >>= 1) {
            for (int t = threadIdx.x; t < CHUNK / 2; t += 1024) {
                unsigned i  = ((t & ~(j - 1)) << 1) | (t & (j - 1));
                unsigned ix = i | j;
                bool up = (((gbase + i) & k) == 0);
                float a = s[i], b = s[ix];
                if ((a > b) == up) { s[i] = b; s[ix] = a; }
            }
            __syncthreads();
        }
    }
    for (int t = threadIdx.x; t < CHUNK; t += 1024) g_sort[base + t] = s[t];
}

__global__ void bitonic_global_step(unsigned k, unsigned j) {
    unsigned t   = blockIdx.x * blockDim.x + threadIdx.x;   // 64 rows * 65536 comparators
    unsigned tr  = t & (ROW_ / 2 - 1);
    unsigned row = t >> (LOG_ROW - 1);
    unsigned i   = ((tr & ~(j - 1)) << 1) | (tr & (j - 1));
    unsigned ix  = i | j;
    size_t off = (size_t)row << LOG_ROW;
    bool up = ((i & k) == 0);
    float a = g_sort[off + i], b = g_sort[off + ix];
    if ((a > b) == up) { g_sort[off + i] = b; g_sort[off + ix] = a; }
}

__global__ void __launch_bounds__(1024) bitonic_shared_merge(unsigned k) {
    __shared__ float s[CHUNK];
    size_t base = (size_t)blockIdx.x * CHUNK;
    unsigned gbase = (unsigned)(base & (ROW_ - 1));
    bool up = ((gbase & k) == 0);    // k > CHUNK -> constant per chunk
    for (int t = threadIdx.x; t < CHUNK; t += 1024) s[t] = g_sort[base + t];
    __syncthreads();
    for (unsigned j = CHUNK / 2; j > 0; j >>= 1) {
        for (int t = threadIdx.x; t < CHUNK / 2; t += 1024) {
            unsigned i  = ((t & ~(j - 1)) << 1) | (t & (j - 1));
            unsigned ix = i | j;
            float a = s[i], b = s[ix];
            if ((a > b) == up) { s[i] = b; s[ix] = a; }
        }
        __syncthreads();
    }
    for (int t = threadIdx.x; t < CHUNK; t += 1024) g_sort[base + t] = s[t];
}

// ---------------- EMD ---------------------------------------------------------
__global__ void emd_kernel() {
    int b = blockIdx.y;
    const float* p = g_sort + (size_t)b * ROW_;
    const float* g = g_sort + (size_t)(B_ + b) * ROW_;
    double local = 0.0;
    for (int i = blockIdx.x * blockDim.x + threadIdx.x; i < ROW_;
         i += gridDim.x * blockDim.x)
        local += (double)fabsf(p[i] - g[i]);
    double s = blockReduceSum(local);
    if (threadIdx.x == 0) atomicAdd(&g_emd[b], s);
}

// ---------------- finalize -----------------------------------------------------
__global__ void final_kernel(float* out) {
    int b = threadIdx.x;
    if (b < B_) {
        double mae = g_acc[0] / (double)TOT_;
        double ch  = g_acc[1] / (double)(B_ * N_) + g_acc[2] / (double)(N_ * N_);
        out[b] = (float)(mae + ch + g_emd[b] / (double)ROW_);
    }
}

// ---------------- launch --------------------------------------------------------
extern "C" void kernel_launch(void* const* d_in, const int* in_sizes, int n_in,
                              void* d_out, int out_size) {
    const float* pred = (const float*)d_in[0];
    const float* tgt  = (const float*)d_in[1];
    float* out = (float*)d_out;

    init_kernel<<<512, 256>>>();
    mae_copy_kernel<<<2048, 256>>>(pred, tgt);
    norms_kernel<<<8192, 256>>>(pred, tgt);
    dist_kernel<<<dim3(8, 8, 4), 256>>>(pred, tgt);
    reduce_colmin_kernel<<<64, 256>>>();
    reduce_minB_kernel<<<512, 256>>>();

    // bitonic sort: 64 rows x 131072 (both tensors in one buffer)
    bitonic_local_sort<<<2 * TOT_ / CHUNK, 1024>>>();
    for (unsigned k = 2 * CHUNK; k <= (unsigned)ROW_; k <<= 1) {
        for (unsigned j = k >> 1; j >= (unsigned)CHUNK; j >>= 1)
            bitonic_global_step<<<(2 * TOT_ / 2) / 256, 256>>>(k, j);
        bitonic_shared_merge<<<2 * TOT_ / CHUNK, 1024>>>(k);
    }

    emd_kernel<<<dim3(64, B_), 256>>>();
    final_kernel<<<1, 32>>>(out);
}

// round 5
// speedup vs baseline: 1.7542x; 1.7542x over previous
#include <cuda_runtime.h>
#include <math.h>

#define B_    32
#define N_    1024
#define D_    128
#define ROW_  (N_ * D_)        // 131072 elements per batch row
#define TOT_  (B_ * ROW_)      // 4194304 elements per tensor
#define KBINS (1 << 17)        // histogram bins per batch
#define VRANGE 8.0f            // values clamped to [-8, 8)
#define LOG_ROW 17

// ---------------- scratch (static device globals: no allocs allowed) -------
__device__ int    g_hist[B_ * KBINS];  // signed counts: +pred, -target (16 MB)
__device__ float  g_normP[B_ * N_];
__device__ float  g_normG[B_ * N_];
__device__ int    g_colmin[B_ * N_];   // min over n per (b,m), float bits
__device__ int    g_minB[N_ * N_];     // min over b per (n,m), float bits (4 MB)
__device__ double g_acc[3];            // 0: mae sum, 1: colmin sum, 2: minB sum
__device__ double g_emd[B_];

// ---------------- helpers ---------------------------------------------------
__device__ __forceinline__ double blockReduceSum(double v) {
    __shared__ double s[32];
    int lane = threadIdx.x & 31, w = threadIdx.x >> 5;
    #pragma unroll
    for (int o = 16; o; o >>= 1) v += __shfl_down_sync(0xffffffffu, v, o);
    if (lane == 0) s[w] = v;
    __syncthreads();
    int nw = (blockDim.x + 31) >> 5;
    v = (threadIdx.x < nw) ? s[threadIdx.x] : 0.0;
    if (w == 0) {
        #pragma unroll
        for (int o = 16; o; o >>= 1) v += __shfl_down_sync(0xffffffffu, v, o);
    }
    return v;
}

// ---------------- init -------------------------------------------------------
__global__ void init_kernel() {
    int tid = blockIdx.x * blockDim.x + threadIdx.x;
    int stride = gridDim.x * blockDim.x;
    for (int i = tid; i < B_ * KBINS; i += stride) g_hist[i] = 0;
    for (int i = tid; i < N_ * N_; i += stride) g_minB[i] = 0x7F800000;
    for (int i = tid; i < B_ * N_; i += stride) g_colmin[i] = 0x7F800000;
    if (tid < 3)  g_acc[tid] = 0.0;
    if (tid < B_) g_emd[tid] = 0.0;
}

// ---------------- MAE + histogram build ---------------------------------------
__global__ void mae_hist_kernel(const float* __restrict__ pred,
                                const float* __restrict__ tgt) {
    const float scale = (float)KBINS / (2.0f * VRANGE);
    int tid = blockIdx.x * blockDim.x + threadIdx.x;
    int stride = gridDim.x * blockDim.x;
    double local = 0.0;
    for (int i = tid; i < TOT_; i += stride) {
        float p = pred[i], g = tgt[i];
        local += (double)fabsf(p - g);
        int b = i >> LOG_ROW;
        int bp = (int)((p + VRANGE) * scale);
        int bg = (int)((g + VRANGE) * scale);
        bp = min(max(bp, 0), KBINS - 1);
        bg = min(max(bg, 0), KBINS - 1);
        atomicAdd(&g_hist[(b << 17) + bp], 1);
        atomicAdd(&g_hist[(b << 17) + bg], -1);
    }
    double s = blockReduceSum(local);
    if (threadIdx.x == 0) atomicAdd(&g_acc[0], s);
}

// ---------------- EMD: scan signed histogram, integrate |CDF diff| ------------
// one block (1024 threads) per batch; each thread owns 128 contiguous bins.
__global__ void __launch_bounds__(1024) emd_scan_kernel() {
    __shared__ int warpsum[32];
    const int b = blockIdx.x;
    const int* h = g_hist + (b << 17);
    const int tid = threadIdx.x, lane = tid & 31, w = tid >> 5;
    const int per = KBINS / 1024;       // 128
    const int base = tid * per;

    int total = 0;
    #pragma unroll 8
    for (int i = 0; i < per; i++) total += h[base + i];

    // inclusive warp scan of per-thread totals
    int s = total;
    #pragma unroll
    for (int o = 1; o < 32; o <<= 1) {
        int t = __shfl_up_sync(0xffffffffu, s, o);
        if (lane >= o) s += t;
    }
    if (lane == 31) warpsum[w] = s;
    __syncthreads();
    if (w == 0) {
        int ws = warpsum[lane];
        #pragma unroll
        for (int o = 1; o < 32; o <<= 1) {
            int t = __shfl_up_sync(0xffffffffu, ws, o);
            if (lane >= o) ws += t;
        }
        warpsum[lane] = ws;
    }
    __syncthreads();
    int excl = s - total + (w ? warpsum[w - 1] : 0);   // exclusive prefix

    long long cum = excl;
    double acc = 0.0;
    #pragma unroll 8
    for (int i = 0; i < per; i++) {
        cum += h[base + i];
        acc += fabs((double)cum);
    }
    double blocksum = blockReduceSum(acc);
    if (tid == 0) {
        const double width = (2.0 * (double)VRANGE) / (double)KBINS;
        g_emd[b] = blocksum * width / (double)ROW_;
    }
}

// ---------------- row squared norms ------------------------------------------
__global__ void norms_kernel(const float* __restrict__ pred,
                             const float* __restrict__ tgt) {
    int gw = (blockIdx.x * blockDim.x + threadIdx.x) >> 5;
    int lane = threadIdx.x & 31;
    if (gw >= 2 * B_ * N_) return;
    const float* src = (gw < B_ * N_) ? pred : tgt;
    int row = gw & (B_ * N_ - 1);
    const float* p = src + (size_t)row * D_;
    float v0 = p[lane], v1 = p[lane + 32], v2 = p[lane + 64], v3 = p[lane + 96];
    float s = v0 * v0 + v1 * v1 + v2 * v2 + v3 * v3;
    #pragma unroll
    for (int o = 16; o; o >>= 1) s += __shfl_down_sync(0xffffffffu, s, o);
    if (lane == 0) ((gw < B_ * N_) ? g_normP : g_normG)[row] = s;
}

// ---------------- distance GEMM + fused min reductions -----------------------
// grid (8 m-tiles, 8 n-tiles, 4 batch-groups), block 256 (16x16), 8x8 micro.
__global__ void __launch_bounds__(256, 1)
dist_kernel(const float* __restrict__ pred, const float* __restrict__ tgt) {
    __shared__ float As[32][129];   // As[k][n] transposed, pad 1 -> conflict-free
    __shared__ float Bs[32][129];
    const int tx = threadIdx.x & 15;
    const int ty = threadIdx.x >> 4;
    const int tm = blockIdx.x, tn = blockIdx.y;

    float rmin[8][8];
    #pragma unroll
    for (int i = 0; i < 8; i++)
        #pragma unroll
        for (int j = 0; j < 8; j++) rmin[i][j] = __int_as_float(0x7F800000);

    for (int bb = 0; bb < 8; ++bb) {
        int b = blockIdx.z * 8 + bb;
        const float* A  = pred + ((size_t)b * N_ + tn * 128) * D_;
        const float* Bp = tgt  + ((size_t)b * N_ + tm * 128) * D_;

        float acc[8][8];
        #pragma unroll
        for (int i = 0; i < 8; i++)
            #pragma unroll
            for (int j = 0; j < 8; j++) acc[i][j] = 0.f;

        for (int kc = 0; kc < D_; kc += 32) {
            __syncthreads();
            #pragma unroll
            for (int it = 0; it < 4; ++it) {
                int e = threadIdx.x + it * 256;         // 1024 float4 slots
                int r = e >> 3, kq = e & 7;
                float4 va = *reinterpret_cast<const float4*>(A + r * D_ + kc + kq * 4);
                As[kq * 4 + 0][r] = va.x; As[kq * 4 + 1][r] = va.y;
                As[kq * 4 + 2][r] = va.z; As[kq * 4 + 3][r] = va.w;
                float4 vb = *reinterpret_cast<const float4*>(Bp + r * D_ + kc + kq * 4);
                Bs[kq * 4 + 0][r] = vb.x; Bs[kq * 4 + 1][r] = vb.y;
                Bs[kq * 4 + 2][r] = vb.z; Bs[kq * 4 + 3][r] = vb.w;
            }
            __syncthreads();
            #pragma unroll 4
            for (int k = 0; k < 32; ++k) {
                float ra[8], rb[8];
                #pragma unroll
                for (int i = 0; i < 8; i++) ra[i] = As[k][ty + 16 * i];
                #pragma unroll
                for (int j = 0; j < 8; j++) rb[j] = Bs[k][tx + 16 * j];
                #pragma unroll
                for (int i = 0; i < 8; i++)
                    #pragma unroll
                    for (int j = 0; j < 8; j++)
                        acc[i][j] = fmaf(ra[i], rb[j], acc[i][j]);
            }
        }

        float nA[8], nB[8], cmin[8];
        #pragma unroll
        for (int i = 0; i < 8; i++) nA[i] = g_normP[b * N_ + tn * 128 + ty + 16 * i];
        #pragma unroll
        for (int j = 0; j < 8; j++) {
            nB[j] = g_normG[b * N_ + tm * 128 + tx + 16 * j];
            cmin[j] = __int_as_float(0x7F800000);
        }
        #pragma unroll
        for (int i = 0; i < 8; i++)
            #pragma unroll
            for (int j = 0; j < 8; j++) {
                float sq = nA[i] + nB[j] - 2.f * acc[i][j];
                float d = sqrtf(fmaxf(sq, 1e-12f));
                rmin[i][j] = fminf(rmin[i][j], d);
                cmin[j]    = fminf(cmin[j], d);
            }

        // reduce cmin over ty (16 rows) in shared, then atomicMin to g_colmin
        __syncthreads();
        float* red = &As[0][0];       // needs 16*128 floats, As has 32*129
        #pragma unroll
        for (int j = 0; j < 8; j++) red[ty * 128 + tx + 16 * j] = cmin[j];
        __syncthreads();
        #pragma unroll
        for (int s = 8; s >= 1; s >>= 1) {
            if (ty < s) {
                #pragma unroll
                for (int j = 0; j < 8; j++) {
                    int ml = tx + 16 * j;
                    red[ty * 128 + ml] = fminf(red[ty * 128 + ml],
                                               red[(ty + s) * 128 + ml]);
                }
            }
            __syncthreads();
        }
        if (ty == 0) {
            #pragma unroll
            for (int j = 0; j < 8; j++) {
                int m = tm * 128 + tx + 16 * j;
                atomicMin(&g_colmin[b * N_ + m], __float_as_int(red[tx + 16 * j]));
            }
        }
    }

    // min over b: one atomicMin per element (4 contenders per address, z-groups)
    #pragma unroll
    for (int i = 0; i < 8; i++)
        #pragma unroll
        for (int j = 0; j < 8; j++) {
            int n = tn * 128 + ty + 16 * i;
            int m = tm * 128 + tx + 16 * j;
            atomicMin(&g_minB[n * N_ + m], __float_as_int(rmin[i][j]));
        }
}

// ---------------- chamfer reductions ------------------------------------------
__global__ void reduce_colmin_kernel() {
    int tid = blockIdx.x * blockDim.x + threadIdx.x, stride = gridDim.x * blockDim.x;
    double local = 0.0;
    for (int i = tid; i < B_ * N_; i += stride) local += (double)__int_as_float(g_colmin[i]);
    double s = blockReduceSum(local);
    if (threadIdx.x == 0) atomicAdd(&g_acc[1], s);
}
__global__ void reduce_minB_kernel() {
    int tid = blockIdx.x * blockDim.x + threadIdx.x, stride = gridDim.x * blockDim.x;
    double local = 0.0;
    for (int i = tid; i < N_ * N_; i += stride) local += (double)__int_as_float(g_minB[i]);
    double s = blockReduceSum(local);
    if (threadIdx.x == 0) atomicAdd(&g_acc[2], s);
}

// ---------------- finalize -----------------------------------------------------
__global__ void final_kernel(float* out) {
    int b = threadIdx.x;
    if (b < B_) {
        double mae = g_acc[0] / (double)TOT_;
        double ch  = g_acc[1] / (double)(B_ * N_) + g_acc[2] / (double)(N_ * N_);
        out[b] = (float)(mae + ch + g_emd[b]);
    }
}

// ---------------- launch --------------------------------------------------------
extern "C" void kernel_launch(void* const* d_in, const int* in_sizes, int n_in,
                              void* d_out, int out_size) {
    const float* pred = (const float*)d_in[0];
    const float* tgt  = (const float*)d_in[1];
    float* out = (float*)d_out;

    init_kernel<<<1024, 256>>>();
    mae_hist_kernel<<<2048, 256>>>(pred, tgt);
    norms_kernel<<<8192, 256>>>(pred, tgt);
    dist_kernel<<<dim3(8, 8, 4), 256>>>(pred, tgt);
    reduce_colmin_kernel<<<64, 256>>>();
    reduce_minB_kernel<<<512, 256>>>();
    emd_scan_kernel<<<B_, 1024>>>();
    final_kernel<<<1, 32>>>(out);
}

// round 8
// speedup vs baseline: 3.3422x; 1.9052x over previous
#include <cuda_runtime.h>
#include <cuda_bf16.h>
#include <math.h>
#include <stdint.h>

#define B_    32
#define N_    1024
#define D_    128
#define ROW_  (N_ * D_)
#define TOT_  (B_ * ROW_)
#define KBINS (1 << 17)
#define VRANGE 8.0f
#define ZG    4
#define BPZ   8

// ---------------- scratch ----------------------------------------------------
__device__ int    g_hist[B_ * KBINS];   // 16 MB signed histogram
__device__ uint4  g_ph[TOT_ / 8];       // pred bf16 (8 MB), row-major [b*N+row][128]
__device__ uint4  g_th[TOT_ / 8];       // target bf16 (8 MB)
__device__ float  g_normP[B_ * N_];
__device__ float  g_normG[B_ * N_];
__device__ int    g_colmin[B_ * N_];    // min-sq over n per (b,m)
__device__ int    g_minB[N_ * N_];      // min-sq over b per (m,n)
__device__ double g_acc[3];
__device__ double g_emd[B_];

// ---------------- helpers ----------------------------------------------------
__device__ __forceinline__ double blockReduceSum(double v) {
    __shared__ double s[32];
    int lane = threadIdx.x & 31, w = threadIdx.x >> 5;
    #pragma unroll
    for (int o = 16; o; o >>= 1) v += __shfl_down_sync(0xffffffffu, v, o);
    if (lane == 0) s[w] = v;
    __syncthreads();
    int nw = (blockDim.x + 31) >> 5;
    v = (threadIdx.x < nw) ? s[threadIdx.x] : 0.0;
    if (w == 0) {
        #pragma unroll
        for (int o = 16; o; o >>= 1) v += __shfl_down_sync(0xffffffffu, v, o);
    }
    return v;
}
__device__ __forceinline__ uint32_t smem_u32(const void* p) {
    uint32_t a;
    asm("{ .reg .u64 t; cvta.to.shared.u64 t, %1; cvt.u32.u64 %0, t; }" : "=r"(a) : "l"(p));
    return a;
}
#define CPA16(dst, src) \
    asm volatile("cp.async.cg.shared.global [%0], [%1], 16;" :: "r"(dst), "l"(src))
#define CPA_COMMIT() asm volatile("cp.async.commit_group;" ::: "memory")
#define CPA_WAIT0()  asm volatile("cp.async.wait_group 0;" ::: "memory")

#define LDSM4(r0, r1, r2, r3, a) \
    asm volatile("ldmatrix.sync.aligned.m8n8.x4.shared.b16 {%0,%1,%2,%3}, [%4];" \
                 : "=r"(r0), "=r"(r1), "=r"(r2), "=r"(r3) : "r"(a))
#define MMA16816(d, a, b0, b1) \
    asm volatile("mma.sync.aligned.m16n8k16.row.col.f32.bf16.bf16.f32 " \
                 "{%0,%1,%2,%3},{%4,%5,%6,%7},{%8,%9},{%0,%1,%2,%3};" \
                 : "+f"((d)[0]), "+f"((d)[1]), "+f"((d)[2]), "+f"((d)[3]) \
                 : "r"((a)[0]), "r"((a)[1]), "r"((a)[2]), "r"((a)[3]), \
                   "r"(b0), "r"(b1))

// smem tile: 128 rows x 256B (128 bf16), 32B-group XOR swizzle -> conflict-free
__device__ __forceinline__ uint32_t swz(int r, int c16) {
    return (uint32_t)(r * 256 + ((((c16 >> 1) ^ (r & 7)) << 5) | ((c16 & 1) << 4)));
}

// dist smem: 2 stages x (A 32K | B 32K | snP 512 | snG 512) = 133120 bytes
#define STG_STRIDE 66560
#define OFF_SB     32768
#define OFF_SNP    65536
#define OFF_SNG    66048
#define DIST_SMEM  (2 * STG_STRIDE)

// ---------------- init --------------------------------------------------------
__global__ void init_kernel() {
    int tid = blockIdx.x * blockDim.x + threadIdx.x;
    int stride = gridDim.x * blockDim.x;
    int4 z4 = make_int4(0, 0, 0, 0);
    for (int i = tid; i < B_ * KBINS / 4; i += stride)
        reinterpret_cast<int4*>(g_hist)[i] = z4;
    for (int i = tid; i < N_ * N_; i += stride) g_minB[i] = 0x7F800000;
    for (int i = tid; i < B_ * N_; i += stride) g_colmin[i] = 0x7F800000;
    if (tid < 3) g_acc[tid] = 0.0;
}

// ---------------- prep: MAE + hist + norms + bf16 convert ---------------------
__global__ void prep_kernel(const float* __restrict__ pred,
                            const float* __restrict__ tgt) {
    const float scale = (float)KBINS / (2.0f * VRANGE);
    int gw = (blockIdx.x * blockDim.x + threadIdx.x) >> 5;
    int lane = threadIdx.x & 31;
    int nwarps = (gridDim.x * blockDim.x) >> 5;
    double mae = 0.0;
    for (int row = gw; row < B_ * N_; row += nwarps) {
        float4 p4 = *reinterpret_cast<const float4*>(pred + (size_t)row * D_ + lane * 4);
        float4 g4 = *reinterpret_cast<const float4*>(tgt  + (size_t)row * D_ + lane * 4);
        mae += (double)(fabsf(p4.x - g4.x) + fabsf(p4.y - g4.y) +
                        fabsf(p4.z - g4.z) + fabsf(p4.w - g4.w));
        float np = p4.x * p4.x + p4.y * p4.y + p4.z * p4.z + p4.w * p4.w;
        float ng = g4.x * g4.x + g4.y * g4.y + g4.z * g4.z + g4.w * g4.w;
        #pragma unroll
        for (int o = 16; o; o >>= 1) {
            np += __shfl_down_sync(0xffffffffu, np, o);
            ng += __shfl_down_sync(0xffffffffu, ng, o);
        }
        if (lane == 0) { g_normP[row] = np; g_normG[row] = ng; }
        __nv_bfloat162 p01 = __floats2bfloat162_rn(p4.x, p4.y);
        __nv_bfloat162 p23 = __floats2bfloat162_rn(p4.z, p4.w);
        __nv_bfloat162 g01 = __floats2bfloat162_rn(g4.x, g4.y);
        __nv_bfloat162 g23 = __floats2bfloat162_rn(g4.z, g4.w);
        uint2 up, ug;
        up.x = *reinterpret_cast<uint32_t*>(&p01); up.y = *reinterpret_cast<uint32_t*>(&p23);
        ug.x = *reinterpret_cast<uint32_t*>(&g01); ug.y = *reinterpret_cast<uint32_t*>(&g23);
        reinterpret_cast<uint2*>(g_ph)[(size_t)row * 32 + lane] = up;
        reinterpret_cast<uint2*>(g_th)[(size_t)row * 32 + lane] = ug;
        int b = row >> 10;
        int* h = g_hist + ((size_t)b << 17);
        float pv[4] = {p4.x, p4.y, p4.z, p4.w};
        float gv[4] = {g4.x, g4.y, g4.z, g4.w};
        #pragma unroll
        for (int e = 0; e < 4; e++) {
            int bp = (int)((pv[e] + VRANGE) * scale);
            int bg = (int)((gv[e] + VRANGE) * scale);
            bp = min(max(bp, 0), KBINS - 1);
            bg = min(max(bg, 0), KBINS - 1);
            atomicAdd(&h[bp], 1);
            atomicAdd(&h[bg], -1);
        }
    }
    double s = blockReduceSum(mae);
    if (threadIdx.x == 0) atomicAdd(&g_acc[0], s);
}

// ---------------- distance via mma.sync bf16 ----------------------------------
// grid (8 tm, 8 tn, ZG), 256 threads. A rows = target (m), B rows = pred (n).
// Warp layout 4(M) x 2(N): warp tile 32x64, per warp 2 m-tiles x 8 n-tiles.
__global__ void __launch_bounds__(256, 1) dist_mma_kernel() {
    extern __shared__ char smem[];
    uint32_t sb = smem_u32(smem);
    const int tid = threadIdx.x, wid = tid >> 5, lane = tid & 31;
    const int tm = blockIdx.x, tn = blockIdx.y, bz = blockIdx.z;
    const int mbase = (wid & 3) * 32;          // warp M offset in tile
    const int nbase = (wid >> 2) * 64;         // warp N offset in tile
    const int qrow = lane >> 2;                // row within 8 (quad id)
    const int qcol = (lane & 3) * 2;           // col pair base

    // issue async loads for batch b into stage s
    auto load_batch = [&](int s, int b) {
        uint32_t st = sb + s * STG_STRIDE;
        const uint4* At = g_th + ((size_t)b * N_ + tm * 128) * 16;
        const uint4* Bt = g_ph + ((size_t)b * N_ + tn * 128) * 16;
        #pragma unroll
        for (int i = 0; i < 8; i++) {
            int c = i * 256 + tid;             // 2048 16B chunks per tile
            int r = c >> 4, c16 = c & 15;
            uint32_t off = swz(r, c16);
            CPA16(st + off, At + r * 16 + c16);
            CPA16(st + OFF_SB + off, Bt + r * 16 + c16);
        }
        if (tid < 32)
            CPA16(st + OFF_SNP + tid * 16, g_normP + b * N_ + tn * 128 + tid * 4);
        else if (tid < 64)
            CPA16(st + OFF_SNG + (tid - 32) * 16, g_normG + b * N_ + tm * 128 + (tid - 32) * 4);
        CPA_COMMIT();
    };

    float rmin[16][4];
    #pragma unroll
    for (int t = 0; t < 16; t++)
        #pragma unroll
        for (int e = 0; e < 4; e++) rmin[t][e] = __int_as_float(0x7F800000);

    load_batch(0, bz * BPZ);

    for (int bb = 0; bb < BPZ; bb++) {
        int b = bz * BPZ + bb;
        int s = bb & 1;
        uint32_t st = sb + s * STG_STRIDE;

        CPA_WAIT0();
        __syncthreads();
        if (bb + 1 < BPZ) load_batch(s ^ 1, b + 1);

        float d[16][4];
        #pragma unroll
        for (int t = 0; t < 16; t++)
            #pragma unroll
            for (int e = 0; e < 4; e++) d[t][e] = 0.f;

        #pragma unroll
        for (int ks = 0; ks < 8; ks++) {
            int c16 = ks * 2 + (lane >> 4);
            uint32_t a[2][4], bf[4][4];
            #pragma unroll
            for (int i = 0; i < 2; i++) {
                int r = mbase + i * 16 + (lane & 15);
                LDSM4(a[i][0], a[i][1], a[i][2], a[i][3], st + swz(r, c16));
            }
            #pragma unroll
            for (int jj = 0; jj < 4; jj++) {
                int r = nbase + jj * 16 + (lane & 15);
                LDSM4(bf[jj][0], bf[jj][1], bf[jj][2], bf[jj][3],
                      st + OFF_SB + swz(r, c16));
            }
            #pragma unroll
            for (int i = 0; i < 2; i++)
                #pragma unroll
                for (int j = 0; j < 8; j++) {
                    int jj = j >> 1, sel = j & 1;
                    uint32_t b0 = sel ? bf[jj][1] : bf[jj][0];
                    uint32_t b1 = sel ? bf[jj][3] : bf[jj][2];
                    MMA16816(d[i * 8 + j], a[i], b0, b1);
                }
        }

        // epilogue: sq = nG[m] + nP[n] - 2*dot; update running mins
        const float* snP = reinterpret_cast<const float*>(smem + s * STG_STRIDE + OFF_SNP);
        const float* snG = reinterpret_cast<const float*>(smem + s * STG_STRIDE + OFF_SNG);
        #pragma unroll
        for (int i = 0; i < 2; i++) {
            float ngA = snG[mbase + i * 16 + qrow];
            float ngB = snG[mbase + i * 16 + 8 + qrow];
            float cmin0 = __int_as_float(0x7F800000);
            float cmin1 = cmin0;
            #pragma unroll
            for (int j = 0; j < 8; j++) {
                int idx = i * 8 + j;
                float np0 = snP[nbase + j * 8 + qcol];
                float np1 = snP[nbase + j * 8 + qcol + 1];
                float s00 = fmaxf(fmaf(-2.f, d[idx][0], ngA + np0), 1e-12f);
                float s01 = fmaxf(fmaf(-2.f, d[idx][1], ngA + np1), 1e-12f);
                float s10 = fmaxf(fmaf(-2.f, d[idx][2], ngB + np0), 1e-12f);
                float s11 = fmaxf(fmaf(-2.f, d[idx][3], ngB + np1), 1e-12f);
                rmin[idx][0] = fminf(rmin[idx][0], s00);
                rmin[idx][1] = fminf(rmin[idx][1], s01);
                rmin[idx][2] = fminf(rmin[idx][2], s10);
                rmin[idx][3] = fminf(rmin[idx][3], s11);
                cmin0 = fminf(cmin0, fminf(s00, s01));
                cmin1 = fminf(cmin1, fminf(s10, s11));
            }
            // reduce over quad lanes (cols) -> per-row min over warp's 64 cols
            #pragma unroll
            for (int o = 1; o < 4; o <<= 1) {
                cmin0 = fminf(cmin0, __shfl_xor_sync(0xffffffffu, cmin0, o));
                cmin1 = fminf(cmin1, __shfl_xor_sync(0xffffffffu, cmin1, o));
            }
            if ((lane & 3) == 0) {
                int mg = tm * 128 + mbase + i * 16 + qrow;
                atomicMin(&g_colmin[b * N_ + mg], __float_as_int(cmin0));
                atomicMin(&g_colmin[b * N_ + mg + 8], __float_as_int(cmin1));
            }
        }
        __syncthreads();
    }

    // flush min-over-batches (ZG contenders per address)
    #pragma unroll
    for (int i = 0; i < 2; i++)
        #pragma unroll
        for (int j = 0; j < 8; j++) {
            int idx = i * 8 + j;
            int mg = tm * 128 + mbase + i * 16 + qrow;
            int ng = tn * 128 + nbase + j * 8 + qcol;
            atomicMin(&g_minB[mg * N_ + ng],           __float_as_int(rmin[idx][0]));
            atomicMin(&g_minB[mg * N_ + ng + 1],       __float_as_int(rmin[idx][1]));
            atomicMin(&g_minB[(mg + 8) * N_ + ng],     __float_as_int(rmin[idx][2]));
            atomicMin(&g_minB[(mg + 8) * N_ + ng + 1], __float_as_int(rmin[idx][3]));
        }
}

// ---------------- chamfer reductions ------------------------------------------
__global__ void reduce_colmin_kernel() {
    int tid = blockIdx.x * blockDim.x + threadIdx.x, stride = gridDim.x * blockDim.x;
    double local = 0.0;
    for (int i = tid; i < B_ * N_; i += stride)
        local += (double)sqrtf(__int_as_float(g_colmin[i]));
    double s = blockReduceSum(local);
    if (threadIdx.x == 0) atomicAdd(&g_acc[1], s);
}
__global__ void reduce_minB_kernel() {
    int tid = blockIdx.x * blockDim.x + threadIdx.x, stride = gridDim.x * blockDim.x;
    double local = 0.0;
    for (int i = tid; i < N_ * N_; i += stride)
        local += (double)sqrtf(__int_as_float(g_minB[i]));
    double s = blockReduceSum(local);
    if (threadIdx.x == 0) atomicAdd(&g_acc[2], s);
}

// ---------------- EMD scan ------------------------------------------------------
__global__ void __launch_bounds__(1024) emd_scan_kernel() {
    __shared__ int warpsum[32];
    const int b = blockIdx.x;
    const int* h = g_hist + ((size_t)b << 17);
    const int tid = threadIdx.x, lane = tid & 31, w = tid >> 5;
    const int per = KBINS / 1024;
    const int base = tid * per;

    int total = 0;
    #pragma unroll 8
    for (int i = 0; i < per; i++) total += h[base + i];

    int s = total;
    #pragma unroll
    for (int o = 1; o < 32; o <<= 1) {
        int t = __shfl_up_sync(0xffffffffu, s, o);
        if (lane >= o) s += t;
    }
    if (lane == 31) warpsum[w] = s;
    __syncthreads();
    if (w == 0) {
        int ws = warpsum[lane];
        #pragma unroll
        for (int o = 1; o < 32; o <<= 1) {
            int t = __shfl_up_sync(0xffffffffu, ws, o);
            if (lane >= o) ws += t;
        }
        warpsum[lane] = ws;
    }
    __syncthreads();
    int excl = s - total + (w ? warpsum[w - 1] : 0);

    long long cum = excl;
    double acc = 0.0;
    #pragma unroll 8
    for (int i = 0; i < per; i++) {
        cum += h[base + i];
        acc += fabs((double)cum);
    }
    double blocksum = blockReduceSum(acc);
    if (tid == 0) {
        const double width = (2.0 * (double)VRANGE) / (double)KBINS;
        g_emd[b] = blocksum * width / (double)ROW_;
    }
}

// ---------------- finalize ------------------------------------------------------
__global__ void final_kernel(float* out) {
    int b = threadIdx.x;
    if (b < B_) {
        double mae = g_acc[0] / (double)TOT_;
        double ch  = g_acc[1] / (double)(B_ * N_) + g_acc[2] / (double)(N_ * N_);
        out[b] = (float)(mae + ch + g_emd[b]);
    }
}

// ---------------- launch --------------------------------------------------------
extern "C" void kernel_launch(void* const* d_in, const int* in_sizes, int n_in,
                              void* d_out, int out_size) {
    const float* pred = (const float*)d_in[0];
    const float* tgt  = (const float*)d_in[1];
    float* out = (float*)d_out;

    cudaFuncSetAttribute(dist_mma_kernel,
                         cudaFuncAttributeMaxDynamicSharedMemorySize, DIST_SMEM);

    init_kernel<<<1024, 256>>>();
    prep_kernel<<<512, 256>>>(pred, tgt);
    dist_mma_kernel<<<dim3(8, 8, ZG), 256, DIST_SMEM>>>();
    reduce_colmin_kernel<<<32, 256>>>();
    reduce_minB_kernel<<<512, 256>>>();
    emd_scan_kernel<<<B_, 1024>>>();
    final_kernel<<<1, 32>>>(out);
}

// round 9
// speedup vs baseline: 7.0919x; 2.1219x over previous
#include <cuda_runtime.h>
#include <cuda_bf16.h>
#include <math.h>
#include <stdint.h>

#define B_    32
#define N_    1024
#define D_    128
#define ROW_  (N_ * D_)
#define TOT_  (B_ * ROW_)
#define KBINS (1 << 15)        // 32768 bins, fits 128KB smem as int
#define VRANGE 8.0f
#define ZG    4
#define BPZ   8

// ---------------- scratch ----------------------------------------------------
__device__ uint4  g_ph[TOT_ / 8];       // pred bf16 (8 MB)
__device__ uint4  g_th[TOT_ / 8];       // target bf16 (8 MB)
__device__ float  g_normP[B_ * N_];
__device__ float  g_normG[B_ * N_];
__device__ int    g_colmin[B_ * N_];    // min-sq over n per (b,m)
__device__ int    g_minB[N_ * N_];      // min-sq over b per (m,n)
__device__ double g_acc[3];
__device__ double g_emd[B_];

// ---------------- helpers ----------------------------------------------------
__device__ __forceinline__ double blockReduceSum(double v) {
    __shared__ double s[32];
    int lane = threadIdx.x & 31, w = threadIdx.x >> 5;
    #pragma unroll
    for (int o = 16; o; o >>= 1) v += __shfl_down_sync(0xffffffffu, v, o);
    if (lane == 0) s[w] = v;
    __syncthreads();
    int nw = (blockDim.x + 31) >> 5;
    v = (threadIdx.x < nw) ? s[threadIdx.x] : 0.0;
    if (w == 0) {
        #pragma unroll
        for (int o = 16; o; o >>= 1) v += __shfl_down_sync(0xffffffffu, v, o);
    }
    return v;
}
__device__ __forceinline__ uint32_t smem_u32(const void* p) {
    uint32_t a;
    asm("{ .reg .u64 t; cvta.to.shared.u64 t, %1; cvt.u32.u64 %0, t; }" : "=r"(a) : "l"(p));
    return a;
}
#define CPA16(dst, src) \
    asm volatile("cp.async.cg.shared.global [%0], [%1], 16;" :: "r"(dst), "l"(src))
#define CPA_COMMIT() asm volatile("cp.async.commit_group;" ::: "memory")
#define CPA_WAIT0()  asm volatile("cp.async.wait_group 0;" ::: "memory")

#define LDSM4(r0, r1, r2, r3, a) \
    asm volatile("ldmatrix.sync.aligned.m8n8.x4.shared.b16 {%0,%1,%2,%3}, [%4];" \
                 : "=r"(r0), "=r"(r1), "=r"(r2), "=r"(r3) : "r"(a))
#define MMA16816(d, a, b0, b1) \
    asm volatile("mma.sync.aligned.m16n8k16.row.col.f32.bf16.bf16.f32 " \
                 "{%0,%1,%2,%3},{%4,%5,%6,%7},{%8,%9},{%0,%1,%2,%3};" \
                 : "+f"((d)[0]), "+f"((d)[1]), "+f"((d)[2]), "+f"((d)[3]) \
                 : "r"((a)[0]), "r"((a)[1]), "r"((a)[2]), "r"((a)[3]), \
                   "r"(b0), "r"(b1))

// smem tile: 128 rows x 256B (128 bf16), 32B-group XOR swizzle -> conflict-free
__device__ __forceinline__ uint32_t swz(int r, int c16) {
    return (uint32_t)(r * 256 + ((((c16 >> 1) ^ (r & 7)) << 5) | ((c16 & 1) << 4)));
}

// dist smem: 2 stages x (A 32K | B 32K | snP 512 | snG 512) = 133120 bytes
#define STG_STRIDE 66560
#define OFF_SB     32768
#define OFF_SNP    65536
#define OFF_SNG    66048
#define DIST_SMEM  (2 * STG_STRIDE)
#define PREP_SMEM  (KBINS * 4)

// ---------------- init --------------------------------------------------------
__global__ void init_kernel() {
    int tid = blockIdx.x * blockDim.x + threadIdx.x;
    int stride = gridDim.x * blockDim.x;
    for (int i = tid; i < N_ * N_; i += stride) g_minB[i] = 0x7F800000;
    for (int i = tid; i < B_ * N_; i += stride) g_colmin[i] = 0x7F800000;
    if (tid < 3) g_acc[tid] = 0.0;
}

// ---------------- prep: one block per batch ------------------------------------
// MAE + norms + bf16 convert + smem signed histogram + in-block EMD scan.
__global__ void __launch_bounds__(1024) prep_kernel(const float* __restrict__ pred,
                                                    const float* __restrict__ tgt) {
    extern __shared__ int sh[];                  // KBINS signed counts
    __shared__ int warpsum[32];
    const int b = blockIdx.x;
    const int tid = threadIdx.x, lane = tid & 31, wid = tid >> 5;
    const float scale = (float)KBINS / (2.0f * VRANGE);

    for (int i = tid; i < KBINS; i += 1024) sh[i] = 0;
    __syncthreads();

    double mae = 0.0;
    #pragma unroll 1
    for (int k = 0; k < 32; k++) {
        int row = b * N_ + wid * 32 + k;
        float4 p4 = *reinterpret_cast<const float4*>(pred + (size_t)row * D_ + lane * 4);
        float4 g4 = *reinterpret_cast<const float4*>(tgt  + (size_t)row * D_ + lane * 4);
        mae += (double)(fabsf(p4.x - g4.x) + fabsf(p4.y - g4.y) +
                        fabsf(p4.z - g4.z) + fabsf(p4.w - g4.w));
        float np = p4.x * p4.x + p4.y * p4.y + p4.z * p4.z + p4.w * p4.w;
        float ng = g4.x * g4.x + g4.y * g4.y + g4.z * g4.z + g4.w * g4.w;
        #pragma unroll
        for (int o = 16; o; o >>= 1) {
            np += __shfl_down_sync(0xffffffffu, np, o);
            ng += __shfl_down_sync(0xffffffffu, ng, o);
        }
        if (lane == 0) { g_normP[row] = np; g_normG[row] = ng; }
        __nv_bfloat162 p01 = __floats2bfloat162_rn(p4.x, p4.y);
        __nv_bfloat162 p23 = __floats2bfloat162_rn(p4.z, p4.w);
        __nv_bfloat162 g01 = __floats2bfloat162_rn(g4.x, g4.y);
        __nv_bfloat162 g23 = __floats2bfloat162_rn(g4.z, g4.w);
        uint2 up, ug;
        up.x = *reinterpret_cast<uint32_t*>(&p01); up.y = *reinterpret_cast<uint32_t*>(&p23);
        ug.x = *reinterpret_cast<uint32_t*>(&g01); ug.y = *reinterpret_cast<uint32_t*>(&g23);
        reinterpret_cast<uint2*>(g_ph)[(size_t)row * 32 + lane] = up;
        reinterpret_cast<uint2*>(g_th)[(size_t)row * 32 + lane] = ug;
        float pv[4] = {p4.x, p4.y, p4.z, p4.w};
        float gv[4] = {g4.x, g4.y, g4.z, g4.w};
        #pragma unroll
        for (int e = 0; e < 4; e++) {
            int bp = (int)((pv[e] + VRANGE) * scale);
            int bg = (int)((gv[e] + VRANGE) * scale);
            bp = min(max(bp, 0), KBINS - 1);
            bg = min(max(bg, 0), KBINS - 1);
            atomicAdd(&sh[bp], 1);
            atomicAdd(&sh[bg], -1);
        }
    }
    double ms = blockReduceSum(mae);
    if (tid == 0) atomicAdd(&g_acc[0], ms);
    __syncthreads();                              // hist complete & visible

    // ---- in-block EMD scan over sh[] ----
    const int per = KBINS / 1024;                 // 32
    const int base = tid * per;
    int total = 0;
    #pragma unroll
    for (int i = 0; i < per; i++) total += sh[base + i];

    int s = total;
    #pragma unroll
    for (int o = 1; o < 32; o <<= 1) {
        int t = __shfl_up_sync(0xffffffffu, s, o);
        if (lane >= o) s += t;
    }
    if (lane == 31) warpsum[wid] = s;
    __syncthreads();
    if (wid == 0) {
        int ws = warpsum[lane];
        #pragma unroll
        for (int o = 1; o < 32; o <<= 1) {
            int t = __shfl_up_sync(0xffffffffu, ws, o);
            if (lane >= o) ws += t;
        }
        warpsum[lane] = ws;
    }
    __syncthreads();
    int excl = s - total + (wid ? warpsum[wid - 1] : 0);

    long long cum = excl;
    double acc = 0.0;
    #pragma unroll
    for (int i = 0; i < per; i++) {
        cum += sh[base + i];
        acc += fabs((double)cum);
    }
    double bs = blockReduceSum(acc);
    if (tid == 0) {
        const double width = (2.0 * (double)VRANGE) / (double)KBINS;
        g_emd[b] = bs * width / (double)ROW_;
    }
}

// ---------------- distance via mma.sync bf16 ----------------------------------
__global__ void __launch_bounds__(256, 1) dist_mma_kernel() {
    extern __shared__ char smem[];
    uint32_t sb = smem_u32(smem);
    const int tid = threadIdx.x, wid = tid >> 5, lane = tid & 31;
    const int tm = blockIdx.x, tn = blockIdx.y, bz = blockIdx.z;
    const int mbase = (wid & 3) * 32;
    const int nbase = (wid >> 2) * 64;
    const int qrow = lane >> 2;
    const int qcol = (lane & 3) * 2;

    auto load_batch = [&](int s, int b) {
        uint32_t st = sb + s * STG_STRIDE;
        const uint4* At = g_th + ((size_t)b * N_ + tm * 128) * 16;
        const uint4* Bt = g_ph + ((size_t)b * N_ + tn * 128) * 16;
        #pragma unroll
        for (int i = 0; i < 8; i++) {
            int c = i * 256 + tid;
            int r = c >> 4, c16 = c & 15;
            uint32_t off = swz(r, c16);
            CPA16(st + off, At + r * 16 + c16);
            CPA16(st + OFF_SB + off, Bt + r * 16 + c16);
        }
        if (tid < 32)
            CPA16(st + OFF_SNP + tid * 16, g_normP + b * N_ + tn * 128 + tid * 4);
        else if (tid < 64)
            CPA16(st + OFF_SNG + (tid - 32) * 16, g_normG + b * N_ + tm * 128 + (tid - 32) * 4);
        CPA_COMMIT();
    };

    float rmin[16][4];
    #pragma unroll
    for (int t = 0; t < 16; t++)
        #pragma unroll
        for (int e = 0; e < 4; e++) rmin[t][e] = __int_as_float(0x7F800000);

    load_batch(0, bz * BPZ);

    for (int bb = 0; bb < BPZ; bb++) {
        int b = bz * BPZ + bb;
        int s = bb & 1;
        uint32_t st = sb + s * STG_STRIDE;

        CPA_WAIT0();
        __syncthreads();
        if (bb + 1 < BPZ) load_batch(s ^ 1, b + 1);

        float d[16][4];
        #pragma unroll
        for (int t = 0; t < 16; t++)
            #pragma unroll
            for (int e = 0; e < 4; e++) d[t][e] = 0.f;

        #pragma unroll
        for (int ks = 0; ks < 8; ks++) {
            int c16 = ks * 2 + (lane >> 4);
            uint32_t a[2][4], bf[4][4];
            #pragma unroll
            for (int i = 0; i < 2; i++) {
                int r = mbase + i * 16 + (lane & 15);
                LDSM4(a[i][0], a[i][1], a[i][2], a[i][3], st + swz(r, c16));
            }
            #pragma unroll
            for (int jj = 0; jj < 4; jj++) {
                int r = nbase + jj * 16 + (lane & 15);
                LDSM4(bf[jj][0], bf[jj][1], bf[jj][2], bf[jj][3],
                      st + OFF_SB + swz(r, c16));
            }
            #pragma unroll
            for (int i = 0; i < 2; i++)
                #pragma unroll
                for (int j = 0; j < 8; j++) {
                    int jj = j >> 1, sel = j & 1;
                    uint32_t b0 = sel ? bf[jj][1] : bf[jj][0];
                    uint32_t b1 = sel ? bf[jj][3] : bf[jj][2];
                    MMA16816(d[i * 8 + j], a[i], b0, b1);
                }
        }

        const float* snP = reinterpret_cast<const float*>(smem + s * STG_STRIDE + OFF_SNP);
        const float* snG = reinterpret_cast<const float*>(smem + s * STG_STRIDE + OFF_SNG);
        #pragma unroll
        for (int i = 0; i < 2; i++) {
            float ngA = snG[mbase + i * 16 + qrow];
            float ngB = snG[mbase + i * 16 + 8 + qrow];
            float cmin0 = __int_as_float(0x7F800000);
            float cmin1 = cmin0;
            #pragma unroll
            for (int j = 0; j < 8; j++) {
                int idx = i * 8 + j;
                float np0 = snP[nbase + j * 8 + qcol];
                float np1 = snP[nbase + j * 8 + qcol + 1];
                float s00 = fmaxf(fmaf(-2.f, d[idx][0], ngA + np0), 1e-12f);
                float s01 = fmaxf(fmaf(-2.f, d[idx][1], ngA + np1), 1e-12f);
                float s10 = fmaxf(fmaf(-2.f, d[idx][2], ngB + np0), 1e-12f);
                float s11 = fmaxf(fmaf(-2.f, d[idx][3], ngB + np1), 1e-12f);
                rmin[idx][0] = fminf(rmin[idx][0], s00);
                rmin[idx][1] = fminf(rmin[idx][1], s01);
                rmin[idx][2] = fminf(rmin[idx][2], s10);
                rmin[idx][3] = fminf(rmin[idx][3], s11);
                cmin0 = fminf(cmin0, fminf(s00, s01));
                cmin1 = fminf(cmin1, fminf(s10, s11));
            }
            #pragma unroll
            for (int o = 1; o < 4; o <<= 1) {
                cmin0 = fminf(cmin0, __shfl_xor_sync(0xffffffffu, cmin0, o));
                cmin1 = fminf(cmin1, __shfl_xor_sync(0xffffffffu, cmin1, o));
            }
            if ((lane & 3) == 0) {
                int mg = tm * 128 + mbase + i * 16 + qrow;
                atomicMin(&g_colmin[b * N_ + mg], __float_as_int(cmin0));
                atomicMin(&g_colmin[b * N_ + mg + 8], __float_as_int(cmin1));
            }
        }
        __syncthreads();
    }

    #pragma unroll
    for (int i = 0; i < 2; i++)
        #pragma unroll
        for (int j = 0; j < 8; j++) {
            int idx = i * 8 + j;
            int mg = tm * 128 + mbase + i * 16 + qrow;
            int ng = tn * 128 + nbase + j * 8 + qcol;
            atomicMin(&g_minB[mg * N_ + ng],           __float_as_int(rmin[idx][0]));
            atomicMin(&g_minB[mg * N_ + ng + 1],       __float_as_int(rmin[idx][1]));
            atomicMin(&g_minB[(mg + 8) * N_ + ng],     __float_as_int(rmin[idx][2]));
            atomicMin(&g_minB[(mg + 8) * N_ + ng + 1], __float_as_int(rmin[idx][3]));
        }
}

// ---------------- fused chamfer reductions -------------------------------------
__global__ void __launch_bounds__(1024) reduce_kernel() {
    double local = 0.0;
    if (blockIdx.x < 64) {
        int tid = blockIdx.x * 1024 + threadIdx.x;
        const int stride = 64 * 1024;
        for (int i = tid; i < N_ * N_; i += stride)
            local += (double)sqrtf(__int_as_float(g_minB[i]));
        double s = blockReduceSum(local);
        if (threadIdx.x == 0) atomicAdd(&g_acc[2], s);
    } else {
        int tid = (blockIdx.x - 64) * 1024 + threadIdx.x;
        const int stride = 8 * 1024;
        for (int i = tid; i < B_ * N_; i += stride)
            local += (double)sqrtf(__int_as_float(g_colmin[i]));
        double s = blockReduceSum(local);
        if (threadIdx.x == 0) atomicAdd(&g_acc[1], s);
    }
}

// ---------------- finalize ------------------------------------------------------
__global__ void final_kernel(float* out) {
    int b = threadIdx.x;
    if (b < B_) {
        double mae = g_acc[0] / (double)TOT_;
        double ch  = g_acc[1] / (double)(B_ * N_) + g_acc[2] / (double)(N_ * N_);
        out[b] = (float)(mae + ch + g_emd[b]);
    }
}

// ---------------- launch --------------------------------------------------------
extern "C" void kernel_launch(void* const* d_in, const int* in_sizes, int n_in,
                              void* d_out, int out_size) {
    const float* pred = (const float*)d_in[0];
    const float* tgt  = (const float*)d_in[1];
    float* out = (float*)d_out;

    cudaFuncSetAttribute(prep_kernel,
                         cudaFuncAttributeMaxDynamicSharedMemorySize, PREP_SMEM);
    cudaFuncSetAttribute(dist_mma_kernel,
                         cudaFuncAttributeMaxDynamicSharedMemorySize, DIST_SMEM);

    init_kernel<<<512, 256>>>();
    prep_kernel<<<B_, 1024, PREP_SMEM>>>(pred, tgt);
    dist_mma_kernel<<<dim3(8, 8, ZG), 256, DIST_SMEM>>>();
    reduce_kernel<<<72, 1024>>>();
    final_kernel<<<1, 32>>>(out);
}

// round 10
// speedup vs baseline: 10.8351x; 1.5278x over previous
#include <cuda_runtime.h>
#include <cuda_bf16.h>
#include <math.h>
#include <stdint.h>

#define B_    32
#define N_    1024
#define D_    128
#define ROW_  (N_ * D_)
#define TOT_  (B_ * ROW_)
#define KBINS (1 << 15)
#define VRANGE 8.0f
#define ZG    2
#define BPZ   16

// ---------------- scratch ----------------------------------------------------
__device__ uint4  g_ph[TOT_ / 8];       // pred bf16, swizzled 32KB-tile layout
__device__ uint4  g_th[TOT_ / 8];       // target bf16, swizzled 32KB-tile layout
__device__ int    g_hist[B_ * KBINS];   // 4 MB signed histogram
__device__ float  g_normP[B_ * N_];
__device__ float  g_normG[B_ * N_];
__device__ int    g_colmin[B_ * N_];
__device__ int    g_minB[N_ * N_];
__device__ double g_acc[3];
__device__ double g_emd[B_];

// ---------------- helpers ----------------------------------------------------
__device__ __forceinline__ float blockReduceSumF(float v) {
    __shared__ float s[32];
    int lane = threadIdx.x & 31, w = threadIdx.x >> 5;
    #pragma unroll
    for (int o = 16; o; o >>= 1) v += __shfl_down_sync(0xffffffffu, v, o);
    if (lane == 0) s[w] = v;
    __syncthreads();
    int nw = (blockDim.x + 31) >> 5;
    v = (threadIdx.x < nw) ? s[threadIdx.x] : 0.f;
    if (w == 0) {
        #pragma unroll
        for (int o = 16; o; o >>= 1) v += __shfl_down_sync(0xffffffffu, v, o);
    }
    return v;
}
__device__ __forceinline__ uint32_t smem_u32(const void* p) {
    uint32_t a;
    asm("{ .reg .u64 t; cvta.to.shared.u64 t, %1; cvt.u32.u64 %0, t; }" : "=r"(a) : "l"(p));
    return a;
}
#define BULK_G2S(dst, src, bytes, mbar) \
    asm volatile("cp.async.bulk.shared::cluster.global.mbarrier::complete_tx::bytes " \
                 "[%0], [%1], %2, [%3];" \
                 :: "r"(dst), "l"(src), "r"((uint32_t)(bytes)), "r"(mbar) : "memory")
#define MB_INIT(mb, c) asm volatile("mbarrier.init.shared.b64 [%0], %1;" :: "r"(mb), "r"((uint32_t)(c)) : "memory")
#define MB_EXPECT(mb, bytes) asm volatile("mbarrier.arrive.expect_tx.shared.b64 _, [%0], %1;" :: "r"(mb), "r"((uint32_t)(bytes)) : "memory")
#define MB_WAIT(mb, ph) do {                                                       \
    uint32_t _m = (mb), _p = (ph), _d;                                             \
    asm volatile("{\n\t.reg .pred p;\n\t"                                          \
        "mbarrier.try_wait.parity.acquire.cta.shared::cta.b64 p, [%1], %2;\n\t"    \
        "selp.b32 %0, 1, 0, p;\n\t}" : "=r"(_d) : "r"(_m), "r"(_p) : "memory");    \
    if (!_d) {                                                                     \
        asm volatile("{\n\t.reg .pred P1;\n\tWL_%=:\n\t"                           \
            "mbarrier.try_wait.parity.acquire.cta.shared::cta.b64 P1, [%0], %1, 0x989680;\n\t" \
            "@P1 bra.uni WD_%=;\n\tbra.uni WL_%=;\n\tWD_%=:\n\t}"                  \
            :: "r"(_m), "r"(_p) : "memory");                                       \
    }                                                                              \
} while (0)

#define LDSM4(r0, r1, r2, r3, a) \
    asm volatile("ldmatrix.sync.aligned.m8n8.x4.shared.b16 {%0,%1,%2,%3}, [%4];" \
                 : "=r"(r0), "=r"(r1), "=r"(r2), "=r"(r3) : "r"(a))
#define MMA16816(d, a, b0, b1) \
    asm volatile("mma.sync.aligned.m16n8k16.row.col.f32.bf16.bf16.f32 " \
                 "{%0,%1,%2,%3},{%4,%5,%6,%7},{%8,%9},{%0,%1,%2,%3};" \
                 : "+f"((d)[0]), "+f"((d)[1]), "+f"((d)[2]), "+f"((d)[3]) \
                 : "r"((a)[0]), "r"((a)[1]), "r"((a)[2]), "r"((a)[3]), \
                   "r"(b0), "r"(b1))

// tile: 128 rows x 256B, 32B-group XOR swizzle -> conflict-free ldmatrix
__device__ __forceinline__ uint32_t swz(int r, int c16) {
    return (uint32_t)(r * 256 + ((((c16 >> 1) ^ (r & 7)) << 5) | ((c16 & 1) << 4)));
}

// dist smem: 2 stages x (A 32K | B 32K | snP 512 | snG 512) + 2 mbarriers
#define STG_STRIDE 66560
#define OFF_SB     32768
#define OFF_SNP    65536
#define OFF_SNG    66048
#define OFF_MBAR   (2 * STG_STRIDE)
#define DIST_SMEM  (2 * STG_STRIDE + 32)
#define STG_BYTES  66560
#define PREP_SMEM  (KBINS * 4)

// ---------------- init --------------------------------------------------------
__global__ void init_kernel() {
    int tid = blockIdx.x * blockDim.x + threadIdx.x;
    int stride = gridDim.x * blockDim.x;
    int4 z4 = make_int4(0, 0, 0, 0);
    for (int i = tid; i < B_ * KBINS / 4; i += stride)
        reinterpret_cast<int4*>(g_hist)[i] = z4;
    for (int i = tid; i < N_ * N_; i += stride) g_minB[i] = 0x7F800000;
    for (int i = tid; i < B_ * N_; i += stride) g_colmin[i] = 0x7F800000;
    if (tid < 3) g_acc[tid] = 0.0;
}

// ---------------- prep: 4 blocks per batch ------------------------------------
// MAE + norms + swizzled bf16 convert + smem partial hist -> global hist.
__global__ void __launch_bounds__(1024) prep_kernel(const float* __restrict__ pred,
                                                    const float* __restrict__ tgt) {
    extern __shared__ int sh[];                   // KBINS signed counts
    const int b = blockIdx.x >> 2, q = blockIdx.x & 3;
    const int tid = threadIdx.x, lane = tid & 31, wid = tid >> 5;
    const float scale = (float)KBINS / (2.0f * VRANGE);

    for (int i = tid; i < KBINS; i += 1024) sh[i] = 0;
    __syncthreads();

    float maef = 0.f;
    #pragma unroll 1
    for (int k = 0; k < 8; k++) {
        int gr = b * N_ + q * 256 + wid * 8 + k;
        float4 p4 = *reinterpret_cast<const float4*>(pred + (size_t)gr * D_ + lane * 4);
        float4 g4 = *reinterpret_cast<const float4*>(tgt  + (size_t)gr * D_ + lane * 4);
        maef += fabsf(p4.x - g4.x) + fabsf(p4.y - g4.y) +
                fabsf(p4.z - g4.z) + fabsf(p4.w - g4.w);
        float np = p4.x * p4.x + p4.y * p4.y + p4.z * p4.z + p4.w * p4.w;
        float ng = g4.x * g4.x + g4.y * g4.y + g4.z * g4.z + g4.w * g4.w;
        #pragma unroll
        for (int o = 16; o; o >>= 1) {
            np += __shfl_down_sync(0xffffffffu, np, o);
            ng += __shfl_down_sync(0xffffffffu, ng, o);
        }
        if (lane == 0) { g_normP[gr] = np; g_normG[gr] = ng; }
        __nv_bfloat162 p01 = __floats2bfloat162_rn(p4.x, p4.y);
        __nv_bfloat162 p23 = __floats2bfloat162_rn(p4.z, p4.w);
        __nv_bfloat162 g01 = __floats2bfloat162_rn(g4.x, g4.y);
        __nv_bfloat162 g23 = __floats2bfloat162_rn(g4.z, g4.w);
        uint2 up, ug;
        up.x = *reinterpret_cast<uint32_t*>(&p01); up.y = *reinterpret_cast<uint32_t*>(&p23);
        ug.x = *reinterpret_cast<uint32_t*>(&g01); ug.y = *reinterpret_cast<uint32_t*>(&g23);
        // swizzled tile layout: tile = gr>>7, row-in-tile = gr&127, chunk = lane>>1
        size_t byteoff = (size_t)(gr >> 7) * 32768
                       + swz(gr & 127, lane >> 1) + (lane & 1) * 8;
        *reinterpret_cast<uint2*>(reinterpret_cast<char*>(g_ph) + byteoff) = up;
        *reinterpret_cast<uint2*>(reinterpret_cast<char*>(g_th) + byteoff) = ug;
        float pv[4] = {p4.x, p4.y, p4.z, p4.w};
        float gv[4] = {g4.x, g4.y, g4.z, g4.w};
        #pragma unroll
        for (int e = 0; e < 4; e++) {
            int bp = (int)((pv[e] + VRANGE) * scale);
            int bg = (int)((gv[e] + VRANGE) * scale);
            bp = min(max(bp, 0), KBINS - 1);
            bg = min(max(bg, 0), KBINS - 1);
            atomicAdd(&sh[bp], 1);
            atomicAdd(&sh[bg], -1);
        }
    }
    float ms = blockReduceSumF(maef);
    if (tid == 0) atomicAdd(&g_acc[0], (double)ms);
    __syncthreads();
    for (int i = tid; i < KBINS; i += 1024) {
        int v = sh[i];
        if (v) atomicAdd(&g_hist[(b << 15) + i], v);
    }
}

// ---------------- EMD scan: one block per batch --------------------------------
__global__ void __launch_bounds__(1024) emd_scan_kernel() {
    __shared__ int warpsum[32];
    const int b = blockIdx.x;
    const int* h = g_hist + ((size_t)b << 15);
    const int tid = threadIdx.x, lane = tid & 31, wid = tid >> 5;
    const int per = KBINS / 1024;                  // 32
    const int base = tid * per;

    int hv[32];
    int total = 0;
    #pragma unroll
    for (int i = 0; i < per; i++) { hv[i] = h[base + i]; total += hv[i]; }

    int s = total;
    #pragma unroll
    for (int o = 1; o < 32; o <<= 1) {
        int t = __shfl_up_sync(0xffffffffu, s, o);
        if (lane >= o) s += t;
    }
    if (lane == 31) warpsum[wid] = s;
    __syncthreads();
    if (wid == 0) {
        int ws = warpsum[lane];
        #pragma unroll
        for (int o = 1; o < 32; o <<= 1) {
            int t = __shfl_up_sync(0xffffffffu, ws, o);
            if (lane >= o) ws += t;
        }
        warpsum[lane] = ws;
    }
    __syncthreads();
    int cum = s - total + (wid ? warpsum[wid - 1] : 0);

    float acc = 0.f;
    #pragma unroll
    for (int i = 0; i < per; i++) {
        cum += hv[i];
        acc += fabsf((float)cum);
    }
    float bs = blockReduceSumF(acc);
    if (tid == 0) {
        const double width = (2.0 * (double)VRANGE) / (double)KBINS;
        g_emd[b] = (double)bs * width / (double)ROW_;
    }
}

// ---------------- distance via mma.sync bf16 + bulk-async loads ----------------
// grid (8 tm, 8 tn, ZG=2), 256 threads; each CTA runs 16 batches.
__global__ void __launch_bounds__(256, 1) dist_mma_kernel() {
    extern __shared__ char smem[];
    uint32_t sb = smem_u32(smem);
    const int tid = threadIdx.x, wid = tid >> 5, lane = tid & 31;
    const int tm = blockIdx.x, tn = blockIdx.y, bz = blockIdx.z;
    const int mbase = (wid & 3) * 32;
    const int nbase = (wid >> 2) * 64;
    const int qrow = lane >> 2;
    const int qcol = (lane & 3) * 2;

    if (tid == 0) {
        MB_INIT(sb + OFF_MBAR, 1);
        MB_INIT(sb + OFF_MBAR + 8, 1);
    }
    __syncthreads();

    auto issue_load = [&](int s, int b) {
        if (tid == 0) {
            uint32_t st = sb + s * STG_STRIDE;
            uint32_t mb = sb + OFF_MBAR + s * 8;
            MB_EXPECT(mb, STG_BYTES);
            const char* At = reinterpret_cast<const char*>(g_th)
                           + (size_t)(b * 8 + tm) * 32768;
            const char* Bt = reinterpret_cast<const char*>(g_ph)
                           + (size_t)(b * 8 + tn) * 32768;
            BULK_G2S(st,           At, 32768, mb);
            BULK_G2S(st + OFF_SB,  Bt, 32768, mb);
            BULK_G2S(st + OFF_SNP, g_normP + b * N_ + tn * 128, 512, mb);
            BULK_G2S(st + OFF_SNG, g_normG + b * N_ + tm * 128, 512, mb);
        }
    };

    float rmin[16][4];
    #pragma unroll
    for (int t = 0; t < 16; t++)
        #pragma unroll
        for (int e = 0; e < 4; e++) rmin[t][e] = __int_as_float(0x7F800000);

    issue_load(0, bz * BPZ);

    for (int bb = 0; bb < BPZ; bb++) {
        int b = bz * BPZ + bb;
        int s = bb & 1;
        uint32_t st = sb + s * STG_STRIDE;

        MB_WAIT(sb + OFF_MBAR + s * 8, (uint32_t)((bb >> 1) & 1));
        if (bb + 1 < BPZ) issue_load(s ^ 1, b + 1);

        float d[16][4];
        #pragma unroll
        for (int t = 0; t < 16; t++)
            #pragma unroll
            for (int e = 0; e < 4; e++) d[t][e] = 0.f;

        #pragma unroll
        for (int ks = 0; ks < 8; ks++) {
            int c16 = ks * 2 + (lane >> 4);
            uint32_t a[2][4], bf[4][4];
            #pragma unroll
            for (int i = 0; i < 2; i++) {
                int r = mbase + i * 16 + (lane & 15);
                LDSM4(a[i][0], a[i][1], a[i][2], a[i][3], st + swz(r, c16));
            }
            #pragma unroll
            for (int jj = 0; jj < 4; jj++) {
                int r = nbase + jj * 16 + (lane & 15);
                LDSM4(bf[jj][0], bf[jj][1], bf[jj][2], bf[jj][3],
                      st + OFF_SB + swz(r, c16));
            }
            #pragma unroll
            for (int i = 0; i < 2; i++)
                #pragma unroll
                for (int j = 0; j < 8; j++) {
                    int jj = j >> 1, sel = j & 1;
                    uint32_t b0 = sel ? bf[jj][1] : bf[jj][0];
                    uint32_t b1 = sel ? bf[jj][3] : bf[jj][2];
                    MMA16816(d[i * 8 + j], a[i], b0, b1);
                }
        }

        const float* snP = reinterpret_cast<const float*>(smem + s * STG_STRIDE + OFF_SNP);
        const float* snG = reinterpret_cast<const float*>(smem + s * STG_STRIDE + OFF_SNG);
        #pragma unroll
        for (int i = 0; i < 2; i++) {
            float ngA = snG[mbase + i * 16 + qrow];
            float ngB = snG[mbase + i * 16 + 8 + qrow];
            float cmin0 = __int_as_float(0x7F800000);
            float cmin1 = cmin0;
            #pragma unroll
            for (int j = 0; j < 8; j++) {
                int idx = i * 8 + j;
                float np0 = snP[nbase + j * 8 + qcol];
                float np1 = snP[nbase + j * 8 + qcol + 1];
                float s00 = fmaxf(fmaf(-2.f, d[idx][0], ngA + np0), 1e-12f);
                float s01 = fmaxf(fmaf(-2.f, d[idx][1], ngA + np1), 1e-12f);
                float s10 = fmaxf(fmaf(-2.f, d[idx][2], ngB + np0), 1e-12f);
                float s11 = fmaxf(fmaf(-2.f, d[idx][3], ngB + np1), 1e-12f);
                rmin[idx][0] = fminf(rmin[idx][0], s00);
                rmin[idx][1] = fminf(rmin[idx][1], s01);
                rmin[idx][2] = fminf(rmin[idx][2], s10);
                rmin[idx][3] = fminf(rmin[idx][3], s11);
                cmin0 = fminf(cmin0, fminf(s00, s01));
                cmin1 = fminf(cmin1, fminf(s10, s11));
            }
            #pragma unroll
            for (int o = 1; o < 4; o <<= 1) {
                cmin0 = fminf(cmin0, __shfl_xor_sync(0xffffffffu, cmin0, o));
                cmin1 = fminf(cmin1, __shfl_xor_sync(0xffffffffu, cmin1, o));
            }
            if ((lane & 3) == 0) {
                int mg = tm * 128 + mbase + i * 16 + qrow;
                atomicMin(&g_colmin[b * N_ + mg], __float_as_int(cmin0));
                atomicMin(&g_colmin[b * N_ + mg + 8], __float_as_int(cmin1));
            }
        }
        __syncthreads();   // stage s fully consumed before it is refilled at bb+2
    }

    #pragma unroll
    for (int i = 0; i < 2; i++)
        #pragma unroll
        for (int j = 0; j < 8; j++) {
            int idx = i * 8 + j;
            int mg = tm * 128 + mbase + i * 16 + qrow;
            int ng = tn * 128 + nbase + j * 8 + qcol;
            atomicMin(&g_minB[mg * N_ + ng],           __float_as_int(rmin[idx][0]));
            atomicMin(&g_minB[mg * N_ + ng + 1],       __float_as_int(rmin[idx][1]));
            atomicMin(&g_minB[(mg + 8) * N_ + ng],     __float_as_int(rmin[idx][2]));
            atomicMin(&g_minB[(mg + 8) * N_ + ng + 1], __float_as_int(rmin[idx][3]));
        }
}

// ---------------- fused chamfer reductions -------------------------------------
__global__ void __launch_bounds__(1024) reduce_kernel() {
    float local = 0.f;
    if (blockIdx.x < 64) {
        const int4* src = reinterpret_cast<const int4*>(g_minB);
        int tid = blockIdx.x * 1024 + threadIdx.x;
        const int stride = 64 * 1024;
        for (int i = tid; i < N_ * N_ / 4; i += stride) {
            int4 v = src[i];
            local += sqrtf(__int_as_float(v.x)) + sqrtf(__int_as_float(v.y))
                   + sqrtf(__int_as_float(v.z)) + sqrtf(__int_as_float(v.w));
        }
        float s = blockReduceSumF(local);
        if (threadIdx.x == 0) atomicAdd(&g_acc[2], (double)s);
    } else {
        const int4* src = reinterpret_cast<const int4*>(g_colmin);
        int tid = (blockIdx.x - 64) * 1024 + threadIdx.x;
        const int stride = 8 * 1024;
        for (int i = tid; i < B_ * N_ / 4; i += stride) {
            int4 v = src[i];
            local += sqrtf(__int_as_float(v.x)) + sqrtf(__int_as_float(v.y))
                   + sqrtf(__int_as_float(v.z)) + sqrtf(__int_as_float(v.w));
        }
        float s = blockReduceSumF(local);
        if (threadIdx.x == 0) atomicAdd(&g_acc[1], (double)s);
    }
}

// ---------------- finalize ------------------------------------------------------
__global__ void final_kernel(float* out) {
    int b = threadIdx.x;
    if (b < B_) {
        double mae = g_acc[0] / (double)TOT_;
        double ch  = g_acc[1] / (double)(B_ * N_) + g_acc[2] / (double)(N_ * N_);
        out[b] = (float)(mae + ch + g_emd[b]);
    }
}

// ---------------- launch --------------------------------------------------------
extern "C" void kernel_launch(void* const* d_in, const int* in_sizes, int n_in,
                              void* d_out, int out_size) {
    const float* pred = (const float*)d_in[0];
    const float* tgt  = (const float*)d_in[1];
    float* out = (float*)d_out;

    cudaFuncSetAttribute(prep_kernel,
                         cudaFuncAttributeMaxDynamicSharedMemorySize, PREP_SMEM);
    cudaFuncSetAttribute(dist_mma_kernel,
                         cudaFuncAttributeMaxDynamicSharedMemorySize, DIST_SMEM);

    init_kernel<<<512, 256>>>();
    prep_kernel<<<4 * B_, 1024, PREP_SMEM>>>(pred, tgt);
    dist_mma_kernel<<<dim3(8, 8, ZG), 256, DIST_SMEM>>>();
    emd_scan_kernel<<<B_, 1024>>>();
    reduce_kernel<<<72, 1024>>>();
    final_kernel<<<1, 32>>>(out);
}